// round 16
// baseline (speedup 1.0000x reference)
#include <cuda_runtime.h>
#include <cuda_fp16.h>
#include <math.h>
#include <stdint.h>

// B=16, T=1024 (MQ=16384), D=512, C=4096, DC=512, A=512, P=512
//
// Weight-space fused pipeline (all fp16 mma.sync, fp32 accum):
//   dual1: k = CE@Wk^T'+bk [4096,512] || WvoT = Wo^T@Wv^T [512,512]
//          + tail CTAs: bvo[p] = wot[p]·bv
//   dual2: kk = k@Wq^T [4096,512]     || voT = WvoT@CE^T+bvo [512,4096]
//          + tail CTAs: t[c] = k[c]·bq
//   scores: e = exp(scale*(ME@kk^T + t)) fp16 + per-block row partial sums
//   pv:     out = (e@voT^T)/rowsum + bo   (rowsum reduced in-kernel prologue)

#define DINL __device__ __forceinline__

// ---------------------------------------------------------------------------
// Scratch
// ---------------------------------------------------------------------------
__device__ __align__(256) __half g_me[16384 * 512];
__device__ __align__(256) __half g_ce[4096 * 512];
__device__ __align__(256) __half g_wkt[512 * 512];   // Wk^T
__device__ __align__(256) __half g_wot[512 * 512];   // Wo^T
__device__ __align__(256) __half g_wq[512 * 512];    // Wq (row-major fp16)
__device__ __align__(256) __half g_wv[512 * 512];    // Wv (row-major fp16)
__device__ __align__(256) __half g_k[4096 * 512];
__device__ __align__(256) __half g_kk[4096 * 512];
__device__ __align__(256) float  g_t[4096];
__device__ __align__(256) __half g_wvoT[512 * 512];
__device__ __align__(256) float  g_bvo[512];
__device__ __align__(256) __half g_voT[512 * 4096];
__device__ __align__(256) __half g_e[(size_t)16384 * 4096];
__device__ __align__(256) float  g_partial[(size_t)16384 * 64];

// ---------------------------------------------------------------------------
// Helpers
// ---------------------------------------------------------------------------
DINL uint32_t smem_u32(const void* p) {
    uint32_t a;
    asm("{ .reg .u64 t; cvta.to.shared.u64 t, %1; cvt.u32.u64 %0, t; }"
        : "=r"(a) : "l"(p));
    return a;
}
DINL void cp16(uint32_t dst, const void* src) {
    asm volatile("cp.async.cg.shared.global [%0], [%1], 16;"
                 :: "r"(dst), "l"(src) : "memory");
}
DINL void cp_commit() { asm volatile("cp.async.commit_group;" ::: "memory"); }
template <int N> DINL void cp_wait() {
    asm volatile("cp.async.wait_group %0;" :: "n"(N) : "memory");
}
DINL void ldsm4(uint32_t* r, uint32_t addr) {
    asm volatile("ldmatrix.sync.aligned.m8n8.x4.shared.b16 {%0,%1,%2,%3}, [%4];"
                 : "=r"(r[0]), "=r"(r[1]), "=r"(r[2]), "=r"(r[3]) : "r"(addr));
}
DINL void mma16816(float* c, const uint32_t* a, uint32_t b0, uint32_t b1) {
    asm volatile(
        "mma.sync.aligned.m16n8k16.row.col.f32.f16.f16.f32 "
        "{%0,%1,%2,%3}, {%4,%5,%6,%7}, {%8,%9}, {%0,%1,%2,%3};"
        : "+f"(c[0]), "+f"(c[1]), "+f"(c[2]), "+f"(c[3])
        : "r"(a[0]), "r"(a[1]), "r"(a[2]), "r"(a[3]), "r"(b0), "r"(b1));
}
DINL uint32_t pack2h(float y0, float y1) {
    __half2 h = __floats2half2_rn(y0, y1);
    return *reinterpret_cast<uint32_t*>(&h);
}

constexpr int ROWB = 144;
constexpr int BM = 128, BN = 128, BK = 64, STAGES = 3;
constexpr int STAGE_B = 128 * ROWB;            // 18432 B
constexpr int SMEM_SZ = 2 * STAGES * STAGE_B;  // 110592 B
constexpr int SMEM_PV = SMEM_SZ + 512;         // + rowsum cache

// ---------------------------------------------------------------------------
// Shared mainloop: accumulates 128x128 tile over K (A,B K-major fp16)
// ---------------------------------------------------------------------------
DINL void gemm_mainloop(
    const __half* __restrict__ A, const __half* __restrict__ B,
    int K, int rowBase, int colBase, uint32_t sb, int t,
    int wm, int wn, uint32_t lrow, uint32_t lcol, float acc[2][8][4])
{
    const int KT = K / BK;
    auto load_chunk = [&](int kt) {
        const int stage = kt % STAGES;
        const size_t kOff = (size_t)kt * BK;
        const uint32_t aBase = sb + stage * STAGE_B;
        const uint32_t bBase = sb + (STAGES + stage) * STAGE_B;
#pragma unroll
        for (int i = 0; i < 4; i++) {
            const int chunk = t + i * 256;
            const int row = chunk >> 3;
            const int c16 = chunk & 7;
            const uint32_t soff = row * ROWB + c16 * 16;
            cp16(aBase + soff, A + (size_t)(rowBase + row) * K + kOff + c16 * 8);
            cp16(bBase + soff, B + (size_t)(colBase + row) * K + kOff + c16 * 8);
        }
        cp_commit();
    };

    for (int i = 0; i < STAGES - 1; i++) load_chunk(i);

    for (int kt = 0; kt < KT; kt++) {
        cp_wait<STAGES - 2>();
        __syncthreads();
        if (kt + STAGES - 1 < KT) load_chunk(kt + STAGES - 1);
        else cp_commit();

        const int stage = kt % STAGES;
        const uint32_t aS = sb + stage * STAGE_B;
        const uint32_t bS = sb + (STAGES + stage) * STAGE_B;

#pragma unroll
        for (int kk = 0; kk < BK; kk += 16) {
            uint32_t a[2][4];
            ldsm4(a[0], aS + (wm * 32 + 0  + lrow) * ROWB + kk * 2 + lcol);
            ldsm4(a[1], aS + (wm * 32 + 16 + lrow) * ROWB + kk * 2 + lcol);
#pragma unroll
            for (int j2 = 0; j2 < 4; j2++) {
                uint32_t b[4];
                ldsm4(b, bS + (wn * 64 + j2 * 16 + lrow) * ROWB + kk * 2 + lcol);
                mma16816(acc[0][2 * j2 + 0], a[0], b[0], b[2]);
                mma16816(acc[1][2 * j2 + 0], a[1], b[0], b[2]);
                mma16816(acc[0][2 * j2 + 1], a[0], b[1], b[3]);
                mma16816(acc[1][2 * j2 + 1], a[1], b[1], b[3]);
            }
        }
        __syncthreads();
    }
}

// ---------------------------------------------------------------------------
// Rowdot body: out[row] = Mh[row,:512] . vec (fp32). One warp per row.
// ---------------------------------------------------------------------------
DINL void rowdot_body(const __half* __restrict__ Mh,
                      const float* __restrict__ vec,
                      float* __restrict__ out, int row, int lane)
{
    const __half* p = Mh + (size_t)row * 512 + lane * 16;
    float s = 0.f;
    const uint4 r0 = *reinterpret_cast<const uint4*>(p);
    const uint4 r1 = *reinterpret_cast<const uint4*>(p + 8);
    const uint32_t w[8] = {r0.x, r0.y, r0.z, r0.w, r1.x, r1.y, r1.z, r1.w};
#pragma unroll
    for (int i = 0; i < 8; i++) {
        float2 h = __half22float2(*reinterpret_cast<const __half2*>(&w[i]));
        s += h.x * __ldg(vec + lane * 16 + 2 * i)
           + h.y * __ldg(vec + lane * 16 + 2 * i + 1);
    }
#pragma unroll
    for (int o = 16; o; o >>= 1) s += __shfl_xor_sync(0xffffffffu, s, o);
    if (lane == 0) out[row] = s;
}

// ---------------------------------------------------------------------------
// Dual GEMM + rowdot tail:
//   blocks [0,nt0): problem 0; [nt0,ntg): problem 1; [ntg,grid): rowdots.
//   bias_mode: 0 none, 1 column, 2 row. GEMM output fp16.
// ---------------------------------------------------------------------------
__global__ __launch_bounds__(256, 2) void mm_dual(
    const __half* A0, const __half* B0, const float* bias0, __half* out0,
    int N0, int K0, int bm0, int nt0,
    const __half* A1, const __half* B1, const float* bias1, __half* out1,
    int N1, int K1, int bm1, int ntg,
    const __half* rdM, const float* rdV, float* rdO)
{
    extern __shared__ char smem[];
    const uint32_t sb = smem_u32(smem);
    const int t = threadIdx.x, wid = t >> 5, lane = t & 31;

    if ((int)blockIdx.x >= ntg) {   // rowdot tail blocks: 8 rows per CTA
        const int row = ((int)blockIdx.x - ntg) * 8 + wid;
        rowdot_body(rdM, rdV, rdO, row, lane);
        return;
    }

    const int wm = wid & 3, wn = wid >> 2;
    const int g = lane >> 2, tq = lane & 3;
    const uint32_t lrow = lane & 15, lcol = (lane >> 4) * 16;

    const __half *A, *B;
    const float* bias;
    __half* out;
    int N, K, bmode, tile;
    if ((int)blockIdx.x < nt0) {
        A = A0; B = B0; bias = bias0; out = out0;
        N = N0; K = K0; bmode = bm0; tile = blockIdx.x;
    } else {
        A = A1; B = B1; bias = bias1; out = out1;
        N = N1; K = K1; bmode = bm1; tile = blockIdx.x - nt0;
    }
    const int ntx = N / BN;
    const int rowBase = (tile / ntx) * BM, colBase = (tile % ntx) * BN;

    float acc[2][8][4];
#pragma unroll
    for (int i = 0; i < 2; i++)
#pragma unroll
        for (int j = 0; j < 8; j++)
#pragma unroll
            for (int c = 0; c < 4; c++) acc[i][j][c] = 0.f;

    gemm_mainloop(A, B, K, rowBase, colBase, sb, t, wm, wn, lrow, lcol, acc);

#pragma unroll
    for (int i = 0; i < 2; i++) {
        const int r0 = rowBase + wm * 32 + i * 16 + g;
        float brA = 0.f, brB = 0.f;
        if (bmode == 2) { brA = __ldg(bias + r0); brB = __ldg(bias + r0 + 8); }
#pragma unroll
        for (int j = 0; j < 8; j++) {
            const int col = colBase + wn * 64 + j * 8 + 2 * tq;
            float y0 = acc[i][j][0], y1 = acc[i][j][1];
            float y2 = acc[i][j][2], y3 = acc[i][j][3];
            if (bmode == 1) {
                const float b0 = __ldg(bias + col), b1 = __ldg(bias + col + 1);
                y0 += b0; y1 += b1; y2 += b0; y3 += b1;
            } else if (bmode == 2) {
                y0 += brA; y1 += brA; y2 += brB; y3 += brB;
            }
            *reinterpret_cast<uint32_t*>(out + (size_t)r0 * N + col) =
                pack2h(y0, y1);
            *reinterpret_cast<uint32_t*>(out + (size_t)(r0 + 8) * N + col) =
                pack2h(y2, y3);
        }
    }
}

// ---------------------------------------------------------------------------
// Scores GEMM: e = exp(alpha*(A@B^T + tbias[col])) -> fp16 + row partial sums
// ---------------------------------------------------------------------------
__global__ __launch_bounds__(256, 2) void mm_scores(
    const __half* __restrict__ A, const __half* __restrict__ B,
    const float* __restrict__ tbias, float alpha,
    __half* __restrict__ outH, float* __restrict__ partial,
    int M, int N, int K)
{
    extern __shared__ char smem[];
    const uint32_t sb = smem_u32(smem);
    const int t = threadIdx.x, wid = t >> 5, lane = t & 31;
    const int wm = wid & 3, wn = wid >> 2;
    const int g = lane >> 2, tq = lane & 3;
    const uint32_t lrow = lane & 15, lcol = (lane >> 4) * 16;
    const int rowBase = blockIdx.y * BM, colBase = blockIdx.x * BN;

    float acc[2][8][4];
#pragma unroll
    for (int i = 0; i < 2; i++)
#pragma unroll
        for (int j = 0; j < 8; j++)
#pragma unroll
            for (int c = 0; c < 4; c++) acc[i][j][c] = 0.f;

    gemm_mainloop(A, B, K, rowBase, colBase, sb, t, wm, wn, lrow, lcol, acc);

#pragma unroll
    for (int i = 0; i < 2; i++) {
        const int r0 = rowBase + wm * 32 + i * 16 + g;
        float s0 = 0.f, s1 = 0.f;
#pragma unroll
        for (int j = 0; j < 8; j++) {
            const int col = colBase + wn * 64 + j * 8 + 2 * tq;
            const float t0 = __ldg(tbias + col), t1 = __ldg(tbias + col + 1);
            float y0 = __expf((acc[i][j][0] + t0) * alpha);
            float y1 = __expf((acc[i][j][1] + t1) * alpha);
            float y2 = __expf((acc[i][j][2] + t0) * alpha);
            float y3 = __expf((acc[i][j][3] + t1) * alpha);
            s0 += y0 + y1; s1 += y2 + y3;
            *reinterpret_cast<uint32_t*>(outH + (size_t)r0 * N + col) =
                pack2h(y0, y1);
            *reinterpret_cast<uint32_t*>(outH + (size_t)(r0 + 8) * N + col) =
                pack2h(y2, y3);
        }
        s0 += __shfl_xor_sync(0xffffffffu, s0, 1);
        s0 += __shfl_xor_sync(0xffffffffu, s0, 2);
        s1 += __shfl_xor_sync(0xffffffffu, s1, 1);
        s1 += __shfl_xor_sync(0xffffffffu, s1, 2);
        if (tq == 0) {
            const int slot = blockIdx.x * 2 + wn;
            partial[(size_t)r0 * 64 + slot] = s0;
            partial[(size_t)(r0 + 8) * 64 + slot] = s1;
        }
    }
}

// ---------------------------------------------------------------------------
// PV+out GEMM: out = (A@B^T)/rowsum + bias(col), fp32 out.
// Rowsums reduced from partials in an smem prologue (no separate kernel).
// ---------------------------------------------------------------------------
__global__ __launch_bounds__(256, 2) void mm_pv(
    const __half* __restrict__ A, const __half* __restrict__ B,
    const float* __restrict__ bias, const float* __restrict__ partial,
    float* __restrict__ outF, int M, int N, int K)
{
    extern __shared__ char smem[];
    const uint32_t sb = smem_u32(smem);
    float* rs = reinterpret_cast<float*>(smem + SMEM_SZ);  // [128]
    const int t = threadIdx.x, wid = t >> 5, lane = t & 31;
    const int wm = wid & 3, wn = wid >> 2;
    const int g = lane >> 2, tq = lane & 3;
    const uint32_t lrow = lane & 15, lcol = (lane >> 4) * 16;
    const int rowBase = blockIdx.y * BM, colBase = blockIdx.x * BN;

    // prologue: rowsum for this CTA's 128 rows (2 threads per row)
    {
        const int rrow = t >> 1;
        const float* pp = partial + (size_t)(rowBase + rrow) * 64 + (t & 1) * 32;
        float s = 0.f;
#pragma unroll
        for (int i = 0; i < 32; i++) s += pp[i];
        s += __shfl_xor_sync(0xffffffffu, s, 1);
        if ((t & 1) == 0) rs[rrow] = s;
    }
    __syncthreads();

    float acc[2][8][4];
#pragma unroll
    for (int i = 0; i < 2; i++)
#pragma unroll
        for (int j = 0; j < 8; j++)
#pragma unroll
            for (int c = 0; c < 4; c++) acc[i][j][c] = 0.f;

    gemm_mainloop(A, B, K, rowBase, colBase, sb, t, wm, wn, lrow, lcol, acc);

#pragma unroll
    for (int i = 0; i < 2; i++) {
        const int lr = wm * 32 + i * 16 + g;
        const int r0 = rowBase + lr;
        const float rsA = 1.f / rs[lr];
        const float rsB = 1.f / rs[lr + 8];
#pragma unroll
        for (int j = 0; j < 8; j++) {
            const int col = colBase + wn * 64 + j * 8 + 2 * tq;
            const float b0 = __ldg(bias + col), b1 = __ldg(bias + col + 1);
            *reinterpret_cast<float2*>(outF + (size_t)r0 * N + col) =
                make_float2(acc[i][j][0] * rsA + b0, acc[i][j][1] * rsA + b1);
            *reinterpret_cast<float2*>(outF + (size_t)(r0 + 8) * N + col) =
                make_float2(acc[i][j][2] * rsB + b0, acc[i][j][3] * rsB + b1);
        }
    }
}

// ---------------------------------------------------------------------------
// fp32 -> fp16 elementwise, two tensors of different sizes (z select)
// ---------------------------------------------------------------------------
__global__ void convert2b_half_kernel(const float* __restrict__ i0, int n0,
                                      const float* __restrict__ i1, int n1,
                                      __half* __restrict__ o0,
                                      __half* __restrict__ o1)
{
    const float* in = blockIdx.z ? i1 : i0;
    __half* o = blockIdx.z ? o1 : o0;
    const int n4 = blockIdx.z ? n1 : n0;
    int i = blockIdx.x * blockDim.x + threadIdx.x;
    if (i >= n4) return;
    float4 v = reinterpret_cast<const float4*>(in)[i];
    reinterpret_cast<uint2*>(o)[i] =
        make_uint2(pack2h(v.x, v.y), pack2h(v.z, v.w));
}

// ---------------------------------------------------------------------------
// Fused transpose of two [512,512] weights (z selects tensor)
// ---------------------------------------------------------------------------
__global__ void transpose2_half_kernel(const float* __restrict__ w0,
                                       const float* __restrict__ w1,
                                       __half* __restrict__ o0,
                                       __half* __restrict__ o1)
{
    const float* in = blockIdx.z ? w1 : w0;
    __half* out = blockIdx.z ? o1 : o0;
    __shared__ float tile[32][33];
    const int cb = blockIdx.x * 32, r0 = blockIdx.y * 32;
    const int tx = threadIdx.x, ty = threadIdx.y;
#pragma unroll
    for (int i = ty; i < 32; i += 8)
        tile[i][tx] = in[(size_t)(r0 + i) * 512 + cb + tx];
    __syncthreads();
#pragma unroll
    for (int i = ty; i < 32; i += 8)
        out[(size_t)(cb + i) * 512 + r0 + tx] = __float2half_rn(tile[tx][i]);
}

// ---------------------------------------------------------------------------
// Launch  (scores GEMM is launch index 5 for ncu -s 5 -c 1; here it is #5)
// ---------------------------------------------------------------------------
extern "C" void kernel_launch(void* const* d_in, const int* in_sizes, int n_in,
                              void* d_out, int out_size)
{
    const float* me = (const float*)d_in[0];
    const float* ce = (const float*)d_in[1];
    const float* Wq = (const float*)d_in[2];
    const float* bq = (const float*)d_in[3];
    const float* Wk = (const float*)d_in[4];
    const float* bk = (const float*)d_in[5];
    const float* Wv = (const float*)d_in[6];
    const float* bv = (const float*)d_in[7];
    const float* Wo = (const float*)d_in[8];
    const float* bo = (const float*)d_in[9];
    float* out = (float*)d_out;

    cudaFuncSetAttribute(mm_dual,   cudaFuncAttributeMaxDynamicSharedMemorySize, SMEM_SZ);
    cudaFuncSetAttribute(mm_scores, cudaFuncAttributeMaxDynamicSharedMemorySize, SMEM_SZ);
    cudaFuncSetAttribute(mm_pv,     cudaFuncAttributeMaxDynamicSharedMemorySize, SMEM_PV);

    __half *meH, *ceH, *wkt, *wot, *wq, *wv, *k, *kk, *wvoT, *voT, *e;
    float *tb, *bvo, *partial;
    cudaGetSymbolAddress((void**)&meH, g_me);
    cudaGetSymbolAddress((void**)&ceH, g_ce);
    cudaGetSymbolAddress((void**)&wkt, g_wkt);
    cudaGetSymbolAddress((void**)&wot, g_wot);
    cudaGetSymbolAddress((void**)&wq, g_wq);
    cudaGetSymbolAddress((void**)&wv, g_wv);
    cudaGetSymbolAddress((void**)&k, g_k);
    cudaGetSymbolAddress((void**)&kk, g_kk);
    cudaGetSymbolAddress((void**)&tb, g_t);
    cudaGetSymbolAddress((void**)&wvoT, g_wvoT);
    cudaGetSymbolAddress((void**)&bvo, g_bvo);
    cudaGetSymbolAddress((void**)&voT, g_voT);
    cudaGetSymbolAddress((void**)&e, g_e);
    cudaGetSymbolAddress((void**)&partial, g_partial);

    const int MQ = 16384, Cn = 4096, Ad = 512, Dd = 512, Pd = 512;
    const float scale = 0.044194173824159216f;  // 1/sqrt(512)
    dim3 tb8(32, 8);

    // 0: me + ce -> fp16 (z-merged)
    convert2b_half_kernel<<<dim3(MQ * Dd / 4 / 256, 1, 2), 256>>>(
        me, MQ * Dd / 4, ce, Cn * Dd / 4, meH, ceH);
    // 1: Wq, Wv -> fp16 (row-major)
    convert2b_half_kernel<<<dim3(256, 1, 2), 256>>>(
        Wq, Dd * Ad / 4, Wv, Dd * Ad / 4, wq, wv);
    // 2: Wk^T, Wo^T
    transpose2_half_kernel<<<dim3(16, 16, 2), tb8>>>(Wk, Wo, wkt, wot);
    // 3: dual1 — k = CE@Wk^T'+bk (128) || WvoT = Wo^T@Wv^T (16) || bvo (64)
    mm_dual<<<144 + 64, 256, SMEM_SZ>>>(
        ceH, wkt, bk, k, Ad, Dd, 1, 128,
        wot, wv, nullptr, wvoT, Dd, Ad, 0, 144,
        wot, bv, bvo);
    // 4: dual2 — kk = k@Wq^T (128) || voT = WvoT@CE^T+bvo (128) || t (512)
    mm_dual<<<256 + 512, 256, SMEM_SZ>>>(
        k, wq, nullptr, kk, Dd, Ad, 0, 128,
        wvoT, ceH, bvo, voT, Cn, Dd, 2, 256,
        k, bq, tb);
    // 5: e = exp(scale*(ME @ kk^T + t)) -> fp16 + partial sums  (ncu target)
    mm_scores<<<dim3(Cn / BN, MQ / BM), 256, SMEM_SZ>>>(
        meH, kk, tb, scale, e, partial, MQ, Cn, Dd);
    // 6: out = (e @ voT^T)/rowsum + bo -> fp32 (rowsum in-kernel)
    mm_pv<<<dim3(Pd / BN, MQ / BM), 256, SMEM_PV>>>(
        e, voT, bo, partial, out, MQ, Pd, Cn);
}

// round 17
// speedup vs baseline: 1.0442x; 1.0442x over previous
#include <cuda_runtime.h>
#include <cuda_fp16.h>
#include <math.h>
#include <stdint.h>

// B=16, T=1024 (MQ=16384), D=512, C=4096, DC=512, A=512, P=512
//
// Weight-space fused pipeline (all fp16 mma.sync, fp32 accum):
//   prologue (1 launch): me,ce,Wq,Wv -> fp16; Wk^T, Wo^T -> fp16
//   dual1: k = CE@Wk^T'+bk [4096,512] || WvoT = Wo^T@Wv^T [512,512]
//   rowdots: t[c] = k[c]·bq,  bvo[p] = wot[p]·bv
//   dual2: kk = k@Wq^T [4096,512]     || voT = WvoT@CE^T+bvo [512,4096]
//   scores: e = exp(scale*(ME@kk^T + t)) fp16 + per-block row partial sums
//   rowinv; pv: out = (e@voT^T)/rowsum + bo

#define DINL __device__ __forceinline__

// ---------------------------------------------------------------------------
// Scratch
// ---------------------------------------------------------------------------
__device__ __align__(256) __half g_me[16384 * 512];
__device__ __align__(256) __half g_ce[4096 * 512];
__device__ __align__(256) __half g_wkt[512 * 512];   // Wk^T
__device__ __align__(256) __half g_wot[512 * 512];   // Wo^T
__device__ __align__(256) __half g_wq[512 * 512];    // Wq (row-major fp16)
__device__ __align__(256) __half g_wv[512 * 512];    // Wv (row-major fp16)
__device__ __align__(256) __half g_k[4096 * 512];
__device__ __align__(256) __half g_kk[4096 * 512];
__device__ __align__(256) float  g_t[4096];
__device__ __align__(256) __half g_wvoT[512 * 512];
__device__ __align__(256) float  g_bvo[512];
__device__ __align__(256) __half g_voT[512 * 4096];
__device__ __align__(256) __half g_e[(size_t)16384 * 4096];
__device__ __align__(256) float  g_partial[(size_t)16384 * 64];
__device__ __align__(256) float  g_invsum[16384];

// ---------------------------------------------------------------------------
// Helpers
// ---------------------------------------------------------------------------
DINL uint32_t smem_u32(const void* p) {
    uint32_t a;
    asm("{ .reg .u64 t; cvta.to.shared.u64 t, %1; cvt.u32.u64 %0, t; }"
        : "=r"(a) : "l"(p));
    return a;
}
DINL void cp16(uint32_t dst, const void* src) {
    asm volatile("cp.async.cg.shared.global [%0], [%1], 16;"
                 :: "r"(dst), "l"(src) : "memory");
}
DINL void cp_commit() { asm volatile("cp.async.commit_group;" ::: "memory"); }
template <int N> DINL void cp_wait() {
    asm volatile("cp.async.wait_group %0;" :: "n"(N) : "memory");
}
DINL void ldsm4(uint32_t* r, uint32_t addr) {
    asm volatile("ldmatrix.sync.aligned.m8n8.x4.shared.b16 {%0,%1,%2,%3}, [%4];"
                 : "=r"(r[0]), "=r"(r[1]), "=r"(r[2]), "=r"(r[3]) : "r"(addr));
}
DINL void mma16816(float* c, const uint32_t* a, uint32_t b0, uint32_t b1) {
    asm volatile(
        "mma.sync.aligned.m16n8k16.row.col.f32.f16.f16.f32 "
        "{%0,%1,%2,%3}, {%4,%5,%6,%7}, {%8,%9}, {%0,%1,%2,%3};"
        : "+f"(c[0]), "+f"(c[1]), "+f"(c[2]), "+f"(c[3])
        : "r"(a[0]), "r"(a[1]), "r"(a[2]), "r"(a[3]), "r"(b0), "r"(b1));
}
DINL uint32_t pack2h(float y0, float y1) {
    __half2 h = __floats2half2_rn(y0, y1);
    return *reinterpret_cast<uint32_t*>(&h);
}

constexpr int ROWB = 144;
constexpr int BM = 128, BN = 128, BK = 64, STAGES = 3;
constexpr int STAGE_B = 128 * ROWB;            // 18432 B
constexpr int SMEM_SZ = 2 * STAGES * STAGE_B;  // 110592 B

// ---------------------------------------------------------------------------
// Shared mainloop (device inline): accumulates 128x128 tile over K
// ---------------------------------------------------------------------------
DINL void gemm_mainloop(
    const __half* __restrict__ A, const __half* __restrict__ B,
    int K, int rowBase, int colBase, uint32_t sb, int t,
    int wm, int wn, uint32_t lrow, uint32_t lcol, float acc[2][8][4])
{
    const int KT = K / BK;
    auto load_chunk = [&](int kt) {
        const int stage = kt % STAGES;
        const size_t kOff = (size_t)kt * BK;
        const uint32_t aBase = sb + stage * STAGE_B;
        const uint32_t bBase = sb + (STAGES + stage) * STAGE_B;
#pragma unroll
        for (int i = 0; i < 4; i++) {
            const int chunk = t + i * 256;
            const int row = chunk >> 3;
            const int c16 = chunk & 7;
            const uint32_t soff = row * ROWB + c16 * 16;
            cp16(aBase + soff, A + (size_t)(rowBase + row) * K + kOff + c16 * 8);
            cp16(bBase + soff, B + (size_t)(colBase + row) * K + kOff + c16 * 8);
        }
        cp_commit();
    };

    for (int i = 0; i < STAGES - 1; i++) load_chunk(i);

    for (int kt = 0; kt < KT; kt++) {
        cp_wait<STAGES - 2>();
        __syncthreads();
        if (kt + STAGES - 1 < KT) load_chunk(kt + STAGES - 1);
        else cp_commit();

        const int stage = kt % STAGES;
        const uint32_t aS = sb + stage * STAGE_B;
        const uint32_t bS = sb + (STAGES + stage) * STAGE_B;

#pragma unroll
        for (int kk = 0; kk < BK; kk += 16) {
            uint32_t a[2][4];
            ldsm4(a[0], aS + (wm * 32 + 0  + lrow) * ROWB + kk * 2 + lcol);
            ldsm4(a[1], aS + (wm * 32 + 16 + lrow) * ROWB + kk * 2 + lcol);
#pragma unroll
            for (int j2 = 0; j2 < 4; j2++) {
                uint32_t b[4];
                ldsm4(b, bS + (wn * 64 + j2 * 16 + lrow) * ROWB + kk * 2 + lcol);
                mma16816(acc[0][2 * j2 + 0], a[0], b[0], b[2]);
                mma16816(acc[1][2 * j2 + 0], a[1], b[0], b[2]);
                mma16816(acc[0][2 * j2 + 1], a[0], b[1], b[3]);
                mma16816(acc[1][2 * j2 + 1], a[1], b[1], b[3]);
            }
        }
        __syncthreads();
    }
}

// ---------------------------------------------------------------------------
// PV+out GEMM: out = (A@B^T)/rowsum + bias(col), fp32 out
// ---------------------------------------------------------------------------
__global__ __launch_bounds__(256, 2) void mm_pv(
    const __half* __restrict__ A, const __half* __restrict__ B,
    const float* __restrict__ bias, const float* __restrict__ rowsum,
    float* __restrict__ outF, int M, int N, int K)
{
    extern __shared__ char smem[];
    const uint32_t sb = smem_u32(smem);
    const int t = threadIdx.x, wid = t >> 5, lane = t & 31;
    const int wm = wid & 3, wn = wid >> 2;
    const int g = lane >> 2, tq = lane & 3;
    const uint32_t lrow = lane & 15, lcol = (lane >> 4) * 16;
    const int rowBase = blockIdx.y * BM, colBase = blockIdx.x * BN;

    float acc[2][8][4];
#pragma unroll
    for (int i = 0; i < 2; i++)
#pragma unroll
        for (int j = 0; j < 8; j++)
#pragma unroll
            for (int c = 0; c < 4; c++) acc[i][j][c] = 0.f;

    gemm_mainloop(A, B, K, rowBase, colBase, sb, t, wm, wn, lrow, lcol, acc);

#pragma unroll
    for (int i = 0; i < 2; i++) {
        const int r0 = rowBase + wm * 32 + i * 16 + g;
        const float rsA = 1.f / __ldg(rowsum + r0);
        const float rsB = 1.f / __ldg(rowsum + r0 + 8);
#pragma unroll
        for (int j = 0; j < 8; j++) {
            const int col = colBase + wn * 64 + j * 8 + 2 * tq;
            const float b0 = __ldg(bias + col), b1 = __ldg(bias + col + 1);
            *reinterpret_cast<float2*>(outF + (size_t)r0 * N + col) =
                make_float2(acc[i][j][0] * rsA + b0, acc[i][j][1] * rsA + b1);
            *reinterpret_cast<float2*>(outF + (size_t)(r0 + 8) * N + col) =
                make_float2(acc[i][j][2] * rsB + b0, acc[i][j][3] * rsB + b1);
        }
    }
}

// ---------------------------------------------------------------------------
// Scores GEMM: e = exp(alpha*(A@B^T + tbias[col])) -> fp16 + row partial sums
// ---------------------------------------------------------------------------
__global__ __launch_bounds__(256, 2) void mm_scores(
    const __half* __restrict__ A, const __half* __restrict__ B,
    const float* __restrict__ tbias, float alpha,
    __half* __restrict__ outH, float* __restrict__ partial,
    int M, int N, int K)
{
    extern __shared__ char smem[];
    const uint32_t sb = smem_u32(smem);
    const int t = threadIdx.x, wid = t >> 5, lane = t & 31;
    const int wm = wid & 3, wn = wid >> 2;
    const int g = lane >> 2, tq = lane & 3;
    const uint32_t lrow = lane & 15, lcol = (lane >> 4) * 16;
    const int rowBase = blockIdx.y * BM, colBase = blockIdx.x * BN;

    float acc[2][8][4];
#pragma unroll
    for (int i = 0; i < 2; i++)
#pragma unroll
        for (int j = 0; j < 8; j++)
#pragma unroll
            for (int c = 0; c < 4; c++) acc[i][j][c] = 0.f;

    gemm_mainloop(A, B, K, rowBase, colBase, sb, t, wm, wn, lrow, lcol, acc);

#pragma unroll
    for (int i = 0; i < 2; i++) {
        const int r0 = rowBase + wm * 32 + i * 16 + g;
        float s0 = 0.f, s1 = 0.f;
#pragma unroll
        for (int j = 0; j < 8; j++) {
            const int col = colBase + wn * 64 + j * 8 + 2 * tq;
            const float t0 = __ldg(tbias + col), t1 = __ldg(tbias + col + 1);
            float y0 = __expf((acc[i][j][0] + t0) * alpha);
            float y1 = __expf((acc[i][j][1] + t1) * alpha);
            float y2 = __expf((acc[i][j][2] + t0) * alpha);
            float y3 = __expf((acc[i][j][3] + t1) * alpha);
            s0 += y0 + y1; s1 += y2 + y3;
            *reinterpret_cast<uint32_t*>(outH + (size_t)r0 * N + col) =
                pack2h(y0, y1);
            *reinterpret_cast<uint32_t*>(outH + (size_t)(r0 + 8) * N + col) =
                pack2h(y2, y3);
        }
        s0 += __shfl_xor_sync(0xffffffffu, s0, 1);
        s0 += __shfl_xor_sync(0xffffffffu, s0, 2);
        s1 += __shfl_xor_sync(0xffffffffu, s1, 1);
        s1 += __shfl_xor_sync(0xffffffffu, s1, 2);
        if (tq == 0) {
            const int slot = blockIdx.x * 2 + wn;
            partial[(size_t)r0 * 64 + slot] = s0;
            partial[(size_t)(r0 + 8) * 64 + slot] = s1;
        }
    }
}

// ---------------------------------------------------------------------------
// Dual GEMM: two independent problems packed into one 1-D grid (R15 form).
// ---------------------------------------------------------------------------
__global__ __launch_bounds__(256, 2) void mm_dual(
    const __half* A0, const __half* B0, const float* bias0, __half* out0,
    int M0, int N0, int K0, int bm0, int nt0,
    const __half* A1, const __half* B1, const float* bias1, __half* out1,
    int M1, int N1, int K1, int bm1)
{
    extern __shared__ char smem[];
    const uint32_t sb = smem_u32(smem);
    const int t = threadIdx.x, wid = t >> 5, lane = t & 31;
    const int wm = wid & 3, wn = wid >> 2;
    const int g = lane >> 2, tq = lane & 3;
    const uint32_t lrow = lane & 15, lcol = (lane >> 4) * 16;

    const __half *A, *B;
    const float* bias;
    __half* out;
    int N, K, bmode, tile;
    if ((int)blockIdx.x < nt0) {
        A = A0; B = B0; bias = bias0; out = out0;
        N = N0; K = K0; bmode = bm0; tile = blockIdx.x;
    } else {
        A = A1; B = B1; bias = bias1; out = out1;
        N = N1; K = K1; bmode = bm1; tile = blockIdx.x - nt0;
    }
    const int ntx = N / BN;
    const int rowBase = (tile / ntx) * BM, colBase = (tile % ntx) * BN;

    float acc[2][8][4];
#pragma unroll
    for (int i = 0; i < 2; i++)
#pragma unroll
        for (int j = 0; j < 8; j++)
#pragma unroll
            for (int c = 0; c < 4; c++) acc[i][j][c] = 0.f;

    gemm_mainloop(A, B, K, rowBase, colBase, sb, t, wm, wn, lrow, lcol, acc);

#pragma unroll
    for (int i = 0; i < 2; i++) {
        const int r0 = rowBase + wm * 32 + i * 16 + g;
        float brA = 0.f, brB = 0.f;
        if (bmode == 2) { brA = __ldg(bias + r0); brB = __ldg(bias + r0 + 8); }
#pragma unroll
        for (int j = 0; j < 8; j++) {
            const int col = colBase + wn * 64 + j * 8 + 2 * tq;
            float y0 = acc[i][j][0], y1 = acc[i][j][1];
            float y2 = acc[i][j][2], y3 = acc[i][j][3];
            if (bmode == 1) {
                const float b0 = __ldg(bias + col), b1 = __ldg(bias + col + 1);
                y0 += b0; y1 += b1; y2 += b0; y3 += b1;
            } else if (bmode == 2) {
                y0 += brA; y1 += brA; y2 += brB; y3 += brB;
            }
            *reinterpret_cast<uint32_t*>(out + (size_t)r0 * N + col) =
                pack2h(y0, y1);
            *reinterpret_cast<uint32_t*>(out + (size_t)(r0 + 8) * N + col) =
                pack2h(y2, y3);
        }
    }
}

// ---------------------------------------------------------------------------
// rowsum[row] = sum over 64 partials (one warp per row)
// ---------------------------------------------------------------------------
__global__ __launch_bounds__(256) void rowinv_kernel(
    const float* __restrict__ partial, float* __restrict__ rowsum)
{
    const int row = blockIdx.x * 8 + (threadIdx.x >> 5);
    const int lane = threadIdx.x & 31;
    const float* p = partial + (size_t)row * 64;
    float s = p[lane] + p[lane + 32];
#pragma unroll
    for (int o = 16; o; o >>= 1) s += __shfl_xor_sync(0xffffffffu, s, o);
    if (lane == 0) rowsum[row] = s;
}

// ---------------------------------------------------------------------------
// Dual rowdot: rows [0,R0): o0[r] = M0[r,:].v0 ; rows >= R0: o1. K=512.
// ---------------------------------------------------------------------------
__global__ __launch_bounds__(256) void rowdot2_kernel(
    const __half* __restrict__ Mh0, const float* __restrict__ v0,
    float* __restrict__ o0, int R0,
    const __half* __restrict__ Mh1, const float* __restrict__ v1,
    float* __restrict__ o1)
{
    int row = blockIdx.x * 8 + (threadIdx.x >> 5);
    const int lane = threadIdx.x & 31;
    const __half* Mh;
    const float* vec;
    float* out;
    if (row < R0) { Mh = Mh0; vec = v0; out = o0; }
    else { row -= R0; Mh = Mh1; vec = v1; out = o1; }
    const __half* p = Mh + (size_t)row * 512 + lane * 16;
    float s = 0.f;
    const uint4 r0 = *reinterpret_cast<const uint4*>(p);
    const uint4 r1 = *reinterpret_cast<const uint4*>(p + 8);
    const uint32_t w[8] = {r0.x, r0.y, r0.z, r0.w, r1.x, r1.y, r1.z, r1.w};
#pragma unroll
    for (int i = 0; i < 8; i++) {
        float2 h = __half22float2(*reinterpret_cast<const __half2*>(&w[i]));
        s += h.x * __ldg(vec + lane * 16 + 2 * i)
           + h.y * __ldg(vec + lane * 16 + 2 * i + 1);
    }
#pragma unroll
    for (int o = 16; o; o >>= 1) s += __shfl_xor_sync(0xffffffffu, s, o);
    if (lane == 0) out[row] = s;
}

// ---------------------------------------------------------------------------
// Prologue über-kernel (1-D grid, 256 thr): block ranges
//   [0,8192):     me  fp32->fp16   (2,097,152 float4)
//   [8192,10240): ce  fp32->fp16   (524,288 float4)
//   [10240,10496): Wq fp32->fp16   (65,536 float4)
//   [10496,10752): Wv fp32->fp16
//   [10752,11008): Wk^T (32x32 tiles, 16x16 grid)
//   [11008,11264): Wo^T
// ---------------------------------------------------------------------------
__global__ __launch_bounds__(256) void prologue_kernel(
    const float* __restrict__ me, const float* __restrict__ ce,
    const float* __restrict__ Wq, const float* __restrict__ Wv,
    const float* __restrict__ Wk, const float* __restrict__ Wo,
    __half* __restrict__ meH, __half* __restrict__ ceH,
    __half* __restrict__ wq, __half* __restrict__ wv,
    __half* __restrict__ wkt, __half* __restrict__ wot)
{
    __shared__ float tile[32][33];
    const int b = blockIdx.x, t = threadIdx.x;

    if (b < 10752) {   // converts
        const float* in;
        __half* o;
        int base;
        if (b < 8192)       { in = me; o = meH; base = b; }
        else if (b < 10240) { in = ce; o = ceH; base = b - 8192; }
        else if (b < 10496) { in = Wq; o = wq;  base = b - 10240; }
        else                { in = Wv; o = wv;  base = b - 10496; }
        const int i = base * 256 + t;
        float4 v = reinterpret_cast<const float4*>(in)[i];
        reinterpret_cast<uint2*>(o)[i] =
            make_uint2(pack2h(v.x, v.y), pack2h(v.z, v.w));
        return;
    }
    // transposes
    const float* in = (b < 11008) ? Wk : Wo;
    __half* out = (b < 11008) ? wkt : wot;
    const int idx = (b < 11008) ? b - 10752 : b - 11008;
    const int cb = (idx & 15) * 32, r0 = (idx >> 4) * 32;
    const int tx = t & 31, ty = t >> 5;   // 32 x 8
#pragma unroll
    for (int i = ty; i < 32; i += 8)
        tile[i][tx] = in[(size_t)(r0 + i) * 512 + cb + tx];
    __syncthreads();
#pragma unroll
    for (int i = ty; i < 32; i += 8)
        out[(size_t)(cb + i) * 512 + r0 + tx] = __float2half_rn(tile[tx][i]);
}

// ---------------------------------------------------------------------------
// Launch
// ---------------------------------------------------------------------------
extern "C" void kernel_launch(void* const* d_in, const int* in_sizes, int n_in,
                              void* d_out, int out_size)
{
    const float* me = (const float*)d_in[0];
    const float* ce = (const float*)d_in[1];
    const float* Wq = (const float*)d_in[2];
    const float* bq = (const float*)d_in[3];
    const float* Wk = (const float*)d_in[4];
    const float* bk = (const float*)d_in[5];
    const float* Wv = (const float*)d_in[6];
    const float* bv = (const float*)d_in[7];
    const float* Wo = (const float*)d_in[8];
    const float* bo = (const float*)d_in[9];
    float* out = (float*)d_out;

    cudaFuncSetAttribute(mm_dual,   cudaFuncAttributeMaxDynamicSharedMemorySize, SMEM_SZ);
    cudaFuncSetAttribute(mm_scores, cudaFuncAttributeMaxDynamicSharedMemorySize, SMEM_SZ);
    cudaFuncSetAttribute(mm_pv,     cudaFuncAttributeMaxDynamicSharedMemorySize, SMEM_SZ);

    __half *meH, *ceH, *wkt, *wot, *wq, *wv, *k, *kk, *wvoT, *voT, *e;
    float *tb, *bvo, *partial, *invsum;
    cudaGetSymbolAddress((void**)&meH, g_me);
    cudaGetSymbolAddress((void**)&ceH, g_ce);
    cudaGetSymbolAddress((void**)&wkt, g_wkt);
    cudaGetSymbolAddress((void**)&wot, g_wot);
    cudaGetSymbolAddress((void**)&wq, g_wq);
    cudaGetSymbolAddress((void**)&wv, g_wv);
    cudaGetSymbolAddress((void**)&k, g_k);
    cudaGetSymbolAddress((void**)&kk, g_kk);
    cudaGetSymbolAddress((void**)&tb, g_t);
    cudaGetSymbolAddress((void**)&wvoT, g_wvoT);
    cudaGetSymbolAddress((void**)&bvo, g_bvo);
    cudaGetSymbolAddress((void**)&voT, g_voT);
    cudaGetSymbolAddress((void**)&e, g_e);
    cudaGetSymbolAddress((void**)&partial, g_partial);
    cudaGetSymbolAddress((void**)&invsum, g_invsum);

    const int MQ = 16384, Cn = 4096, Ad = 512, Dd = 512, Pd = 512;
    const float scale = 0.044194173824159216f;  // 1/sqrt(512)

    // 0: prologue — all converts + transposes in one launch
    prologue_kernel<<<11264, 256>>>(me, ce, Wq, Wv, Wk, Wo,
                                    meH, ceH, wq, wv, wkt, wot);
    // 1: dual1 — k = CE@Wk^T'+bk (128 tiles) || WvoT = Wo^T@Wv^T (16 tiles)
    mm_dual<<<128 + 16, 256, SMEM_SZ>>>(
        ceH, wkt, bk, k, Cn, Ad, Dd, 1, 128,
        wot, wv, nullptr, wvoT, Pd, Dd, Ad, 0);
    // 2: rowdots — t[c]=k[c]·bq (4096 rows) || bvo[p]=wot[p]·bv (512 rows)
    rowdot2_kernel<<<(Cn + Pd) / 8, 256>>>(k, bq, tb, Cn, wot, bv, bvo);
    // 3: dual2 — kk = k@Wq^T (128 tiles) || voT = WvoT@CE^T+bvo (128 tiles)
    mm_dual<<<128 + 128, 256, SMEM_SZ>>>(
        k, wq, nullptr, kk, Cn, Dd, Ad, 0, 128,
        wvoT, ceH, bvo, voT, Pd, Cn, Dd, 2);
    // 4: e = exp(scale*(ME @ kk^T + t)) -> fp16 + partial sums
    mm_scores<<<dim3(Cn / BN, MQ / BM), 256, SMEM_SZ>>>(
        meH, kk, tb, scale, e, partial, MQ, Cn, Dd);
    // 5: invsum
    rowinv_kernel<<<MQ / 8, 256>>>(partial, invsum);
    // 6: out = (e @ voT^T)/rowsum + bo -> fp32
    mm_pv<<<dim3(Pd / BN, MQ / BM), 256, SMEM_SZ>>>(
        e, voT, bo, invsum, out, MQ, Pd, Cn);
}